// round 16
// baseline (speedup 1.0000x reference)
#include <cuda_runtime.h>
#include <cuda_bf16.h>
#include <cstdint>
#include <cstddef>

// Problem constants
constexpr int VOCAB = 32000;
constexpr int DIM   = 1024;
constexpr int BITS  = 15;
constexpr int ROWS  = 4096;   // 4 * 1024
constexpr int KDIM  = 1024;
constexpr int K3    = 3 * KDIM;   // 3072: [hi|hi|lo] x [hi|lo|hi]
constexpr int NCHUNK = K3 / 16;   // 192 k16-chunks

// A in m16n8k16 FRAGMENT order: [mblock 32][chunk 192][sub 8][lane 32][16B]
//   sub = 16-row group within 128-row mblock; per lane 16B = regs {a0,a1,a2,a3}
__device__ uint32_t g_A3F[(size_t)32 * NCHUNK * 1024];      // 25 MB
__device__ __nv_bfloat16 g_B3[(size_t)VOCAB * K3];          // 197 MB
// per-row logit max, order-preserving-encoded fp32 (filled by GEMM epilogue)
__device__ unsigned g_rowmax[ROWS];

// GEMM tiling: 128x128x64, 256 threads (8 warps: 2m x 4n, warp tile 64x32)
// B-only smem stages (A comes straight from L2 via fragment-ordered LDG.128)
constexpr int BM = 128;
constexpr int BN = 128;
constexpr int BK = 64;
constexpr int GEMM_THREADS = 256;
constexpr int B_STAGE = BN * BK * 2;      // 16384 B
constexpr int NSTAGE = 4;
constexpr int GEMM_SMEM = NSTAGE * B_STAGE;   // 65536 B -> 2 CTAs/SM

// ---------------------------------------------------------------------------
// helpers
// ---------------------------------------------------------------------------
__device__ __forceinline__ void cp16(unsigned saddr, const void* gaddr) {
    asm volatile("cp.async.cg.shared.global [%0], [%1], 16;\n"
                 :: "r"(saddr), "l"(gaddr) : "memory");
}
__device__ __forceinline__ void ldsm4(unsigned addr, unsigned& r0, unsigned& r1,
                                      unsigned& r2, unsigned& r3) {
    asm volatile("ldmatrix.sync.aligned.m8n8.x4.shared.b16 {%0,%1,%2,%3}, [%4];"
                 : "=r"(r0), "=r"(r1), "=r"(r2), "=r"(r3) : "r"(addr));
}
__device__ __forceinline__ void mma_bf16(float* c, const unsigned* a, const unsigned* b) {
    asm volatile(
        "mma.sync.aligned.m16n8k16.row.col.f32.bf16.bf16.f32 "
        "{%0,%1,%2,%3}, {%4,%5,%6,%7}, {%8,%9}, {%0,%1,%2,%3};"
        : "+f"(c[0]), "+f"(c[1]), "+f"(c[2]), "+f"(c[3])
        : "r"(a[0]), "r"(a[1]), "r"(a[2]), "r"(a[3]), "r"(b[0]), "r"(b[1]));
}
// byte offset within a [rows x 64bf16] tile, swizzled (128B rows, 16B chunks)
__device__ __forceinline__ unsigned swz(int row, int ch) {
    return (unsigned)((row << 7) + ((ch ^ (row & 7)) << 4));
}
// split two fp32 into bf16x2 hi (e low half, o high half) and bf16x2 lo
__device__ __forceinline__ void cvt_pair(float e, float o, uint32_t& h, uint32_t& l) {
    asm volatile("cvt.rn.bf16x2.f32 %0, %1, %2;" : "=r"(h) : "f"(o), "f"(e));
    float he = __uint_as_float(h << 16);
    float ho = __uint_as_float(h & 0xFFFF0000u);
    float le = e - he;
    float lq = o - ho;
    asm volatile("cvt.rn.bf16x2.f32 %0, %1, %2;" : "=r"(l) : "f"(lq), "f"(le));
}
// order-preserving float<->uint for atomicMax
__device__ __forceinline__ unsigned enc_ord(float f) {
    unsigned u = __float_as_uint(f);
    return (u & 0x80000000u) ? ~u : (u | 0x80000000u);
}
__device__ __forceinline__ float dec_ord(unsigned u) {
    return (u & 0x80000000u) ? __uint_as_float(u & 0x7fffffffu)
                             : __uint_as_float(~u);
}

// ---------------------------------------------------------------------------
// rowmax init
// ---------------------------------------------------------------------------
__global__ void rowmax_init_kernel() {
    g_rowmax[blockIdx.x * 256 + threadIdx.x] = 0u;   // below enc of any float
}

// ---------------------------------------------------------------------------
// convertA: fp32 -> bf16 hi/lo written in m16n8k16 fragment order.
//  m16n8k16 A fragment (row-major): lane l = (row%8)*4 + j holds
//    a0=(row, 2j..2j+1) a1=(row+8, ...) a2=(row, 8+2j..) a3=(row+8, 8+2j..)
//  K3 segments: [hi(0:1024) | hi(1024:2048) | lo(2048:3072)]
// ---------------------------------------------------------------------------
__global__ void convertA_kernel(const float* __restrict__ A) {
    int r = blockIdx.x;            // 0..4095
    int k = threadIdx.x * 4;       // 0..1020 (two bf16x2 pairs)
    float4 f = *reinterpret_cast<const float4*>(A + (size_t)r * KDIM + k);
    uint32_t h0, l0, h1, l1;
    cvt_pair(f.x, f.y, h0, l0);
    cvt_pair(f.z, f.w, h1, l1);

    int mb = r >> 7, sub = (r >> 4) & 7, rr = r & 15;
    char* base = (char*)g_A3F + (size_t)mb * NCHUNK * 4096 + sub * 512
               + ((rr & 7) * 4) * 16 + ((rr >= 8) ? 4 : 0);
    auto st = [&](int p, uint32_t v) {   // p = even k3 position
        int c = p >> 4, kk = p & 15;
        int j = (kk & 7) >> 1;
        *reinterpret_cast<uint32_t*>(
            base + (size_t)c * 4096 + j * 16 + ((kk >= 8) ? 8 : 0)) = v;
    };
    st(k, h0);        st(k + 2, h1);          // seg0: hi
    st(1024 + k, h0); st(1026 + k, h1);       // seg1: hi
    st(2048 + k, l0); st(2050 + k, l1);       // seg2: lo
}

// convertB: row-major K-concat [hi | lo | hi], SW128-compatible (unchanged)
__global__ void convertB_kernel(const float* __restrict__ B) {
    int r = blockIdx.x;
    int k = threadIdx.x * 4;
    float4 f = *reinterpret_cast<const float4*>(B + (size_t)r * KDIM + k);
    uint32_t h0, l0, h1, l1;
    cvt_pair(f.x, f.y, h0, l0);
    cvt_pair(f.z, f.w, h1, l1);
    __nv_bfloat16* dst = g_B3 + (size_t)r * K3;
    *reinterpret_cast<uint2*>(dst + k)            = make_uint2(h0, h1);
    *reinterpret_cast<uint2*>(dst + KDIM + k)     = make_uint2(l0, l1);
    *reinterpret_cast<uint2*>(dst + 2 * KDIM + k) = make_uint2(h0, h1);
}

// ---------------------------------------------------------------------------
// GEMM: logit[4096,32000] = A3 @ B3^T (bf16 HMMA, 3-term split via K=3072)
// A: barrier-free LDG.128 from fragment-ordered g_A3F (L2-resident, L1 reuse)
// B: 4-stage cp.async smem pipeline, one barrier per k-iteration, 2 CTAs/SM
// epilogue: store + fused per-row atomicMax
// ---------------------------------------------------------------------------
__global__ __launch_bounds__(GEMM_THREADS, 2)
void gemm_bf16_kernel(float* __restrict__ C) {
    extern __shared__ char smem[];
    unsigned sbase;
    asm("{ .reg .u64 t; cvta.to.shared.u64 t, %1; cvt.u32.u64 %0, t; }"
        : "=r"(sbase) : "l"(smem));

    int tid  = threadIdx.x;
    int warp = tid >> 5, lane = tid & 31;
    int wm = warp >> 2;        // 0..1  (64 rows each)
    int wn = warp & 3;         // 0..3  (32 cols each)
    int krot = (warp & 1) << 1;

    int bm0 = blockIdx.x * BM;
    int bn0 = blockIdx.y * BN;

    const char* Ab = (const char*)g_A3F
        + (size_t)(bm0 >> 7) * NCHUNK * 4096 + (size_t)wm * 2048 + lane * 16;
    const __nv_bfloat16* Bg = g_B3 + (size_t)bn0 * K3;

    float acc[4][4][4];
#pragma unroll
    for (int mt = 0; mt < 4; ++mt)
#pragma unroll
        for (int nt = 0; nt < 4; ++nt)
#pragma unroll
            for (int i = 0; i < 4; ++i) acc[mt][nt][i] = 0.f;

    const int NK = K3 / BK;    // 48

    // B stage fill: 1024 16B-chunks, 4 per thread
    auto fill = [&](int st, int kt) {
        unsigned sB = sbase + st * B_STAGE;
        int kofs = kt * BK;
#pragma unroll
        for (int j = 0; j < 4; ++j) {
            int c = tid + j * GEMM_THREADS;
            int row = c >> 3, ch = c & 7;
            cp16(sB + swz(row, ch), Bg + (size_t)row * K3 + kofs + ch * 8);
        }
        asm volatile("cp.async.commit_group;" ::: "memory");
    };

    // prologue: stages 0,1,2
    fill(0, 0);
    fill(1, 1);
    fill(2, 2);

    int cur = 0;
    for (int kt = 0; kt < NK; ++kt) {
        asm volatile("cp.async.wait_group 2;" ::: "memory");
        __syncthreads();

        // prefetch kt+3 into stage consumed at kt-1 (safe after barrier)
        if (kt + 3 < NK) {
            fill((cur + 3) & 3, kt + 3);
        } else {
            asm volatile("cp.async.commit_group;" ::: "memory");
        }

        unsigned bB = sbase + cur * B_STAGE;

#pragma unroll
        for (int kx = 0; kx < 4; ++kx) {   // k16 steps within BK=64, staggered
            int kk = (kx + krot) & 3;
            int chunk = kt * 4 + kk;
            // A fragments: one LDG.128 per mt, fragment-ordered, no barrier dep
            unsigned aF[4][4];
            const char* ap = Ab + (size_t)chunk * 4096;
#pragma unroll
            for (int mt = 0; mt < 4; ++mt) {
                uint4 v = __ldg(reinterpret_cast<const uint4*>(ap + mt * 512));
                aF[mt][0] = v.x; aF[mt][1] = v.y;
                aF[mt][2] = v.z; aF[mt][3] = v.w;
            }
            int mat = lane >> 3;
            unsigned bF[4][2];
#pragma unroll
            for (int p = 0; p < 2; ++p) {
                int row = wn * 32 + p * 16 + ((mat >> 1) << 3) + (lane & 7);
                int ch  = 2 * kk + (mat & 1);
                unsigned r0, r1, r2, r3;
                ldsm4(bB + swz(row, ch), r0, r1, r2, r3);
                bF[2 * p][0] = r0; bF[2 * p][1] = r1;
                bF[2 * p + 1][0] = r2; bF[2 * p + 1][1] = r3;
            }
#pragma unroll
            for (int mt = 0; mt < 4; ++mt)
#pragma unroll
                for (int nt = 0; nt < 4; ++nt)
                    mma_bf16(acc[mt][nt], aF[mt], bF[nt]);
        }
        cur = (cur + 1) & 3;
    }

    // epilogue: store + fused per-row max
#pragma unroll
    for (int mt = 0; mt < 4; ++mt) {
        int r0 = bm0 + wm * 64 + mt * 16 + (lane >> 2);
        float m0 = -3.4e38f, m1 = -3.4e38f;
#pragma unroll
        for (int nt = 0; nt < 4; ++nt) {
            int c0 = bn0 + wn * 32 + nt * 8 + ((lane & 3) << 1);
            *reinterpret_cast<float2*>(C + (size_t)r0 * VOCAB + c0) =
                make_float2(acc[mt][nt][0], acc[mt][nt][1]);
            *reinterpret_cast<float2*>(C + (size_t)(r0 + 8) * VOCAB + c0) =
                make_float2(acc[mt][nt][2], acc[mt][nt][3]);
            m0 = fmaxf(m0, fmaxf(acc[mt][nt][0], acc[mt][nt][1]));
            m1 = fmaxf(m1, fmaxf(acc[mt][nt][2], acc[mt][nt][3]));
        }
#pragma unroll
        for (int off = 1; off <= 2; off <<= 1) {
            m0 = fmaxf(m0, __shfl_xor_sync(0xffffffffu, m0, off));
            m1 = fmaxf(m1, __shfl_xor_sync(0xffffffffu, m1, off));
        }
        if ((lane & 3) == 0) {
            atomicMax(&g_rowmax[r0], enc_ord(m0));
            atomicMax(&g_rowmax[r0 + 8], enc_ord(m1));
        }
    }
}

// ---------------------------------------------------------------------------
// Kernel 1: id_emb (row gather) + bit_emb (±1 bits @ weight_bit)
// ---------------------------------------------------------------------------
__global__ void embed_kernel(const int* __restrict__ ids,
                             const float* __restrict__ weight,
                             const float* __restrict__ weight_bit,
                             float* __restrict__ id_emb,
                             float* __restrict__ bit_emb) {
    int r = blockIdx.x;
    int id = ids[r];
    id = min(max(id, 0), VOCAB - 1);
    int d = threadIdx.x * 4;

    float4 w = *reinterpret_cast<const float4*>(weight + (size_t)id * DIM + d);
    *reinterpret_cast<float4*>(id_emb + (size_t)r * DIM + d) = w;

    float4 acc = make_float4(0.f, 0.f, 0.f, 0.f);
#pragma unroll
    for (int k = 0; k < BITS; ++k) {
        float s = ((id >> (BITS - 1 - k)) & 1) ? 1.f : -1.f;
        float4 wb = *reinterpret_cast<const float4*>(weight_bit + k * DIM + d);
        acc.x = fmaf(s, wb.x, acc.x);
        acc.y = fmaf(s, wb.y, acc.y);
        acc.z = fmaf(s, wb.z, acc.z);
        acc.w = fmaf(s, wb.w, acc.w);
    }
    *reinterpret_cast<float4*>(bit_emb + (size_t)r * DIM + d) = acc;
}

// ---------------------------------------------------------------------------
// Kernel 3: logit_w = softmax(logit) @ vocab_bits
// Single exp pass (row max precomputed by GEMM epilogue). FMA-pipe exp.
// v = o*2048 + tid*8 + c: bits 0..2 from c, 3..10 from tid, 11..14 from o.
// ---------------------------------------------------------------------------
__device__ __forceinline__ float exp_fma(float x, float mlog) {
    float y = fmaf(x, 1.4426950408889634f, -mlog);
    y = fmaxf(y, -120.f);
    float t  = __fadd_rn(y, 12582912.f);          // rint via magic
    float yn = __fadd_rn(t, -12582912.f);
    float f  = y - yn;                             // [-0.5, 0.5]
    float p = fmaf(f, 0.0013333558f, 0.0096181291f);
    p = fmaf(f, p, 0.0555041087f);
    p = fmaf(f, p, 0.2402265070f);
    p = fmaf(f, p, 0.6931471806f);
    p = fmaf(f, p, 1.0f);
    int nb = (__float_as_int(t) - 0x4B400000) << 23;
    return __int_as_float(__float_as_int(p) + nb);
}

__global__ void softmax_bits_kernel(const float* __restrict__ logit,
                                    float* __restrict__ out) {
    int row = blockIdx.x;
    const float* x = logit + (size_t)row * VOCAB;
    int tid = threadIdx.x;          // 256
    int warp = tid >> 5, lane = tid & 31;

    __shared__ float sred[8][16];
    __shared__ float sfin[16];

    float mlog = dec_ord(g_rowmax[row]) * 1.4426950408889634f;

    float zt = 0.f, sb0 = 0.f, sb1 = 0.f, sb2 = 0.f;
    float so[4] = {0.f, 0.f, 0.f, 0.f};
#pragma unroll 4
    for (int o = 0; o < 16; ++o) {
        if (o == 15 && tid >= 160) continue;   // 32000 boundary
        const float* p = x + o * 2048 + tid * 8;
        float4 a = *reinterpret_cast<const float4*>(p);
        float4 b = *reinterpret_cast<const float4*>(p + 4);
        float e0 = exp_fma(a.x, mlog), e1 = exp_fma(a.y, mlog);
        float e2 = exp_fma(a.z, mlog), e3 = exp_fma(a.w, mlog);
        float e4 = exp_fma(b.x, mlog), e5 = exp_fma(b.y, mlog);
        float e6 = exp_fma(b.z, mlog), e7 = exp_fma(b.w, mlog);
        float t01 = e0 + e1, t23 = e2 + e3, t45 = e4 + e5, t67 = e6 + e7;
        float b2 = t45 + t67;
        float z8 = (t01 + t23) + b2;
        float b1 = t23 + t67;
        float b0 = (e1 + e3) + (e5 + e7);
        sb0 += b0; sb1 += b1; sb2 += b2; zt += z8;
        if (o & 1) so[0] += z8;
        if (o & 2) so[1] += z8;
        if (o & 4) so[2] += z8;
        if (o & 8) so[3] += z8;
    }

    float s[16];
    s[0] = sb0; s[1] = sb1; s[2] = sb2;
#pragma unroll
    for (int pbit = 0; pbit < 8; ++pbit)
        s[3 + pbit] = ((tid >> pbit) & 1) ? zt : 0.f;
    s[11] = so[0]; s[12] = so[1]; s[13] = so[2]; s[14] = so[3];
    s[15] = zt;

#pragma unroll
    for (int off = 16; off > 0; off >>= 1)
#pragma unroll
        for (int k = 0; k < 16; ++k)
            s[k] += __shfl_xor_sync(0xffffffffu, s[k], off);
    if (lane == 0)
#pragma unroll
        for (int k = 0; k < 16; ++k) sred[warp][k] = s[k];
    __syncthreads();
    if (tid < 16) {
        float v = 0.f;
#pragma unroll
        for (int w = 0; w < 8; ++w) v += sred[w][tid];
        sfin[tid] = v;
    }
    __syncthreads();
    if (tid < 15) {
        float Z = sfin[15];
        out[(size_t)row * 15 + tid] = 2.f * sfin[14 - tid] / Z - 1.f;
    }
}

// ---------------------------------------------------------------------------
// launch
// ---------------------------------------------------------------------------
extern "C" void kernel_launch(void* const* d_in, const int* in_sizes, int n_in,
                              void* d_out, int out_size) {
    const int*   ids        = (const int*)d_in[0];
    const float* tensor     = (const float*)d_in[1];
    const float* weight     = (const float*)d_in[2];
    const float* weight_bit = (const float*)d_in[3];

    float* out     = (float*)d_out;
    float* id_emb  = out;
    float* bit_emb = id_emb + (size_t)ROWS * DIM;
    float* logit   = bit_emb + (size_t)ROWS * DIM;
    float* logit_w = logit + (size_t)ROWS * VOCAB;

    rowmax_init_kernel<<<ROWS / 256, 256>>>();
    embed_kernel<<<ROWS, 256>>>(ids, weight, weight_bit, id_emb, bit_emb);

    convertA_kernel<<<ROWS, 256>>>(tensor);
    convertB_kernel<<<VOCAB, 256>>>(weight);

    static bool attr_set = false;
    if (!attr_set) {
        cudaFuncSetAttribute(gemm_bf16_kernel,
                             cudaFuncAttributeMaxDynamicSharedMemorySize, GEMM_SMEM);
        attr_set = true;
    }
    dim3 grid(ROWS / BM, VOCAB / BN);   // (32, 250), m fastest for B reuse
    gemm_bf16_kernel<<<grid, GEMM_THREADS, GEMM_SMEM>>>(logit);

    softmax_bits_kernel<<<ROWS, 256>>>(logit, logit_w);
}